// round 6
// baseline (speedup 1.0000x reference)
#include <cuda_runtime.h>
#include <cstdint>

#define BM 128
#define BN 128
#define BK 16
#define STAGES 4
#define NTHREADS 256
#define STAGE_WORDS 2048                 // 128*16 floats per operand tile
#define SMEM_BYTES (STAGES * 2 * STAGE_WORDS * 4)   // 64 KB

// ---------------- scratch (device globals; no allocations allowed) ----------
__device__ float g_x[33554432];
__device__ float g_z[33554432];
__device__ float g_q[33554432];
__device__ float g_k[33554432];
__device__ float g_vt[33554432];
__device__ float g_a[33554432];
__device__ float g_w[4194304];   // 4 pre-rounded weight matrices

// ---------------- helpers ----------------------------------------------------
__device__ __forceinline__ uint32_t cvt_tf32(float x) {
    uint32_t r;
    asm("cvt.rna.tf32.f32 %0, %1;" : "=r"(r) : "f"(x));
    return r;
}
__device__ __forceinline__ float round_tf32(float x) {
    return __uint_as_float(cvt_tf32(x));
}
__device__ __forceinline__ void cp_async16(uint32_t dst, const void* src) {
    asm volatile("cp.async.cg.shared.global [%0], [%1], 16;" :: "r"(dst), "l"(src));
}
__device__ __forceinline__ void cp_commit() {
    asm volatile("cp.async.commit_group;");
}
template<int N> __device__ __forceinline__ void cp_wait() {
    asm volatile("cp.async.wait_group %0;" :: "n"(N));
}

// ---------------- tf32 pre-rounding pass -------------------------------------
__global__ void round_kernel(const float* __restrict__ src, float* __restrict__ dst)
{
    int idx = blockIdx.x * blockDim.x + threadIdx.x;
    float4 v = reinterpret_cast<const float4*>(src)[idx];
    v.x = round_tf32(v.x); v.y = round_tf32(v.y);
    v.z = round_tf32(v.z); v.w = round_tf32(v.w);
    reinterpret_cast<float4*>(dst)[idx] = v;
}

// ---------------- gather: x = tf32(item_emb[positives] + pos_emb) ------------
__global__ void gather_kernel(const int* __restrict__ positives,
                              const float* __restrict__ item_emb,
                              const float* __restrict__ pos_emb,
                              float* __restrict__ x)
{
    int idx = blockIdx.x * blockDim.x + threadIdx.x;
    int row = idx >> 8;
    int c4  = idx & 255;
    int l   = row & 1023;
    int item = positives[row];
    float4 a = reinterpret_cast<const float4*>(item_emb)[(long long)item * 256 + c4];
    float4 p = reinterpret_cast<const float4*>(pos_emb)[l * 256 + c4];
    float4 o = make_float4(round_tf32(a.x + p.x), round_tf32(a.y + p.y),
                           round_tf32(a.z + p.z), round_tf32(a.w + p.w));
    reinterpret_cast<float4*>(x)[idx] = o;
}

// ---------------- tf32 tensor-core GEMM (all NT) ------------------------------
// C[m,n] = sum_k A[m,k]*B[n,k]; A rows stride lda, B rows stride ldb, C stride ldc.
// EPI: 0 none, 1 silu->tf32, 2 col-scale gamma/beta->tf32, 3 attention score->tf32
template<int EPI>
__global__ void __launch_bounds__(NTHREADS, 2)
gemm_kernel(const float* __restrict__ Ag, const float* __restrict__ Bg,
            float* __restrict__ Cg, int lda, int ldb, int ldc, int K,
            long long sA, long long sB, long long sC,
            const float* __restrict__ gamma, const float* __restrict__ beta,
            const float* __restrict__ sw, const int* __restrict__ maskv,
            float scale)
{
    extern __shared__ uint32_t smem[];
    uint32_t* As = smem;                          // STAGES * 2048 words
    uint32_t* Bs = smem + STAGES * STAGE_WORDS;   // STAGES * 2048 words

    const int b = blockIdx.z;
    Ag += (long long)b * sA;
    Bg += (long long)b * sB;
    Cg += (long long)b * sC;
    const int* mv = (EPI == 3) ? (maskv + (long long)b * 1024) : maskv;

    const int tid  = threadIdx.x;
    const int lane = tid & 31;
    const int warp = tid >> 5;
    const int wm = (warp >> 2) * 64;   // 2 warps along M
    const int wn = (warp & 3) * 32;    // 4 warps along N
    const int m0 = blockIdx.y * BM;
    const int n0 = blockIdx.x * BN;
    const int tg = lane & 3;           // fragment thread-in-group

    float acc[4][4][4];
    #pragma unroll
    for (int i = 0; i < 4; i++)
        #pragma unroll
        for (int j = 0; j < 4; j++)
            #pragma unroll
            for (int c = 0; c < 4; c++) acc[i][j][c] = 0.f;

    const int nK = K / BK;   // 64

    auto loadStage = [&](int ks, int buf) {
        const int k0 = ks * BK;
        uint32_t abase = (uint32_t)__cvta_generic_to_shared(&As[buf * STAGE_WORDS]);
        uint32_t bbase = (uint32_t)__cvta_generic_to_shared(&Bs[buf * STAGE_WORDS]);
        #pragma unroll
        for (int i = 0; i < 2; i++) {
            int c = tid + i * 256;
            int r = c >> 2, q = c & 3;
            int pq = q ^ ((r >> 1) & 3);
            cp_async16(abase + r * 64 + pq * 16,
                       Ag + (long long)(m0 + r) * lda + k0 + q * 4);
        }
        #pragma unroll
        for (int i = 0; i < 2; i++) {
            int c = tid + i * 256;
            int r = c >> 2, q = c & 3;
            int pq = q ^ ((r >> 1) & 3);
            cp_async16(bbase + r * 64 + pq * 16,
                       Bg + (long long)(n0 + r) * ldb + k0 + q * 4);
        }
        cp_commit();
    };

    loadStage(0, 0);
    loadStage(1, 1);
    loadStage(2, 2);

    for (int j = 0; j < nK; j++) {
        if (j + 3 < nK) {
            loadStage(j + 3, (j + 3) & 3);
            cp_wait<3>();
        } else {
            cp_wait<0>();
        }
        __syncthreads();

        const uint32_t* as = &As[(j & 3) * STAGE_WORDS];
        const uint32_t* bs = &Bs[(j & 3) * STAGE_WORDS];

        #pragma unroll
        for (int kk = 0; kk < BK; kk += 8) {
            // logical k remap: slot tg -> k = kk+2*tg, slot tg+4 -> k = kk+2*tg+1
            // (valid because MMA sums over k; adjacent words enable LDS.64)
            const int cbase = (kk >> 2);     // chunk offset 0 or 2
            uint32_t af[4][4];
            #pragma unroll
            for (int mt = 0; mt < 4; mt++) {
                int r  = wm + mt * 16 + (lane >> 2);
                int r8 = r + 8;
                int ia  = r  * 16 + (((cbase + (tg >> 1)) ^ ((r  >> 1) & 3)) << 2) + ((tg & 1) << 1);
                int ia8 = r8 * 16 + (((cbase + (tg >> 1)) ^ ((r8 >> 1) & 3)) << 2) + ((tg & 1) << 1);
                uint2 va  = *reinterpret_cast<const uint2*>(&as[ia]);
                uint2 va8 = *reinterpret_cast<const uint2*>(&as[ia8]);
                af[mt][0] = va.x;  af[mt][1] = va8.x;
                af[mt][2] = va.y;  af[mt][3] = va8.y;
            }
            uint32_t bf[4][2];
            #pragma unroll
            for (int nt = 0; nt < 4; nt++) {
                int n = wn + nt * 8 + (lane >> 2);
                int ib = n * 16 + (((cbase + (tg >> 1)) ^ ((n >> 1) & 3)) << 2) + ((tg & 1) << 1);
                uint2 vb = *reinterpret_cast<const uint2*>(&bs[ib]);
                bf[nt][0] = vb.x;  bf[nt][1] = vb.y;
            }
            #pragma unroll
            for (int mt = 0; mt < 4; mt++)
                #pragma unroll
                for (int nt = 0; nt < 4; nt++) {
                    asm volatile(
                        "mma.sync.aligned.m16n8k8.row.col.f32.tf32.tf32.f32 "
                        "{%0,%1,%2,%3}, {%4,%5,%6,%7}, {%8,%9}, {%0,%1,%2,%3};"
                        : "+f"(acc[mt][nt][0]), "+f"(acc[mt][nt][1]),
                          "+f"(acc[mt][nt][2]), "+f"(acc[mt][nt][3])
                        : "r"(af[mt][0]), "r"(af[mt][1]), "r"(af[mt][2]), "r"(af[mt][3]),
                          "r"(bf[nt][0]), "r"(bf[nt][1]));
                }
        }
        __syncthreads();
    }

    // ---------------- epilogue ----------------
    #pragma unroll
    for (int mt = 0; mt < 4; mt++) {
        #pragma unroll
        for (int half = 0; half < 2; half++) {
            const int m = m0 + wm + mt * 16 + (lane >> 2) + half * 8;
            #pragma unroll
            for (int nt = 0; nt < 4; nt++) {
                const int n = n0 + wn + nt * 8 + tg * 2;
                float v0 = acc[mt][nt][half * 2 + 0];
                float v1 = acc[mt][nt][half * 2 + 1];
                if (EPI == 1) {
                    v0 = round_tf32(v0 / (1.f + __expf(-v0)));
                    v1 = round_tf32(v1 / (1.f + __expf(-v1)));
                } else if (EPI == 2) {
                    v0 = round_tf32(v0 * gamma[n]     + beta[n]);
                    v1 = round_tf32(v1 * gamma[n + 1] + beta[n + 1]);
                } else if (EPI == 3) {
                    bool keep0 = (m == n)     || (mv[n]     && n     <= m);
                    bool keep1 = (m == n + 1) || (mv[n + 1] && n + 1 <= m);
                    float s0 = keep0 ? v0 * sw[(long long)m * 1024 + n]     : 0.f;
                    float s1 = keep1 ? v1 * sw[(long long)m * 1024 + n + 1] : 0.f;
                    s0 = fmaxf(s0, 0.f);
                    s1 = fmaxf(s1, 0.f);
                    v0 = round_tf32(s0 * s0 * scale);
                    v1 = round_tf32(s1 * s1 * scale);
                }
                *reinterpret_cast<float2*>(&Cg[(long long)m * ldc + n]) = make_float2(v0, v1);
            }
        }
    }
}

// ---------------- launch ------------------------------------------------------
extern "C" void kernel_launch(void* const* d_in, const int* in_sizes, int n_in,
                              void* d_out, int out_size)
{
    const int*   positives = (const int*)  d_in[0];
    const int*   mask      = (const int*)  d_in[1];
    const float* item_emb  = (const float*)d_in[2];
    const float* pos_emb   = (const float*)d_in[3];
    const float* Wz        = (const float*)d_in[4];
    const float* Wv        = (const float*)d_in[5];
    const float* Wq        = (const float*)d_in[6];
    const float* Wk        = (const float*)d_in[7];
    const float* gq        = (const float*)d_in[8];
    const float* bq        = (const float*)d_in[9];
    const float* gk        = (const float*)d_in[10];
    const float* bk        = (const float*)d_in[11];
    const float* sw        = (const float*)d_in[12];
    float* out = (float*)d_out;

    float *x, *z, *q, *k, *vt, *a, *w;
    cudaGetSymbolAddress((void**)&x,  g_x);
    cudaGetSymbolAddress((void**)&z,  g_z);
    cudaGetSymbolAddress((void**)&q,  g_q);
    cudaGetSymbolAddress((void**)&k,  g_k);
    cudaGetSymbolAddress((void**)&vt, g_vt);
    cudaGetSymbolAddress((void**)&a,  g_a);
    cudaGetSymbolAddress((void**)&w,  g_w);

    cudaFuncSetAttribute(gemm_kernel<0>, cudaFuncAttributeMaxDynamicSharedMemorySize, SMEM_BYTES);
    cudaFuncSetAttribute(gemm_kernel<1>, cudaFuncAttributeMaxDynamicSharedMemorySize, SMEM_BYTES);
    cudaFuncSetAttribute(gemm_kernel<2>, cudaFuncAttributeMaxDynamicSharedMemorySize, SMEM_BYTES);
    cudaFuncSetAttribute(gemm_kernel<3>, cudaFuncAttributeMaxDynamicSharedMemorySize, SMEM_BYTES);

    const int L = 1024, M = 32768;
    const long long SL = (long long)L * L;
    float* wz = w;
    float* wv = w + 1048576;
    float* wq = w + 2097152;
    float* wk = w + 3145728;

    round_kernel<<<1024, 256>>>(Wz, wz);
    round_kernel<<<1024, 256>>>(Wv, wv);
    round_kernel<<<1024, 256>>>(Wq, wq);
    round_kernel<<<1024, 256>>>(Wk, wk);
    gather_kernel<<<32768, 256>>>(positives, item_emb, pos_emb, x);

    // z = tf32(silu(x @ Wz^T)):  M=32768, N=1024
    gemm_kernel<1><<<dim3(L / BN, M / BM, 1), NTHREADS, SMEM_BYTES>>>(
        x, wz, z, L, L, L, L, 0, 0, 0, nullptr, nullptr, nullptr, nullptr, 0.f);
    // vt[d,m] = tf32(silu(Wv @ x^T)): M=1024, N=32768, ldc=32768
    gemm_kernel<1><<<dim3(M / BN, L / BM, 1), NTHREADS, SMEM_BYTES>>>(
        wv, x, vt, L, L, M, L, 0, 0, 0, nullptr, nullptr, nullptr, nullptr, 0.f);
    // q = tf32((z @ Wq^T)*gamma_q+beta_q)
    gemm_kernel<2><<<dim3(L / BN, M / BM, 1), NTHREADS, SMEM_BYTES>>>(
        z, wq, q, L, L, L, L, 0, 0, 0, gq, bq, nullptr, nullptr, 0.f);
    // k = tf32((z @ Wk^T)*gamma_k+beta_k)
    gemm_kernel<2><<<dim3(L / BN, M / BM, 1), NTHREADS, SMEM_BYTES>>>(
        z, wk, k, L, L, L, L, 0, 0, 0, gk, bk, nullptr, nullptr, 0.f);
    // a = tf32(relu((q @ k^T)*keep*sparse_w)^2 / (L*D)) per batch
    gemm_kernel<3><<<dim3(L / BN, L / BM, 32), NTHREADS, SMEM_BYTES>>>(
        q, k, a, L, L, L, L, SL, SL, SL, nullptr, nullptr, sw, mask, 1.f / 1048576.f);
    // out = a @ v: B[n-row=d][k=key] = vt[d, b*1024 + key], ldb=32768, sB=1024
    gemm_kernel<0><<<dim3(L / BN, L / BM, 32), NTHREADS, SMEM_BYTES>>>(
        a, vt, out, L, M, L, L, SL, (long long)L, SL, nullptr, nullptr, nullptr, nullptr, 0.f);
}